// round 10
// baseline (speedup 1.0000x reference)
#include <cuda_runtime.h>
#include <cuda_fp16.h>
#include <math.h>
#include <stdint.h>

#define BATCH   8
#define SEQ     1024
#define HID     768
#define NHEADS  12
#define HDIM    64
#define QKV_N   (3*HID)          // 2304
#define MTOT    (BATCH*SEQ)      // 8192

__device__ __half g_x[(size_t)MTOT * HID];        // fp16-rounded x
__device__ __half g_qkv[(size_t)MTOT * QKV_N];    // Q,K channels used
__device__ __half g_vt[(size_t)BATCH * NHEADS * HDIM * SEQ];  // V^T [bh][d][s]
__device__ __half g_o[(size_t)MTOT * HID];        // attention out
__device__ __half g_wt_qkv[(size_t)QKV_N * HID];  // Wqkv^T fp16
__device__ __half g_wt_out[(size_t)HID * HID];    // Wout^T fp16
__device__ float  g_ssf[2 * QKV_N];               // Q-prescaled scale1/shift1

// ---------------------------------------------------------------------------
// helpers
// ---------------------------------------------------------------------------
__device__ __forceinline__ uint32_t smem_u32(const void* p) {
    uint32_t a;
    asm("{ .reg .u64 t; cvta.to.shared.u64 t, %1; cvt.u32.u64 %0, t; }" : "=r"(a) : "l"(p));
    return a;
}
__device__ __forceinline__ uint32_t packh2(float lo, float hi) {
    __half2 h = __floats2half2_rn(lo, hi);
    return *reinterpret_cast<uint32_t*>(&h);
}
__device__ __forceinline__ uint32_t exp2_pack(float lo, float hi) {
    __half2 h = h2exp2(__floats2half2_rn(lo, hi));
    return *reinterpret_cast<uint32_t*>(&h);
}
__device__ __forceinline__ void mma_f16(float* c,
                                        uint32_t a0, uint32_t a1, uint32_t a2, uint32_t a3,
                                        uint32_t b0, uint32_t b1) {
    asm volatile(
        "mma.sync.aligned.m16n8k16.row.col.f32.f16.f16.f32 "
        "{%0,%1,%2,%3}, {%4,%5,%6,%7}, {%8,%9}, {%0,%1,%2,%3};"
        : "+f"(c[0]), "+f"(c[1]), "+f"(c[2]), "+f"(c[3])
        : "r"(a0), "r"(a1), "r"(a2), "r"(a3), "r"(b0), "r"(b1));
}
#define LDSM_X4(r0, r1, r2, r3, addr) \
    asm volatile("ldmatrix.sync.aligned.m8n8.x4.shared.b16 {%0,%1,%2,%3}, [%4];" \
        : "=r"(r0), "=r"(r1), "=r"(r2), "=r"(r3) : "r"(addr))
__device__ __forceinline__ void cp16(uint32_t dst, const void* src) {
    asm volatile("cp.async.cg.shared.global [%0], [%1], 16;" :: "r"(dst), "l"(src));
}
#define CP_COMMIT() asm volatile("cp.async.commit_group;" ::: "memory")
#define CP_WAIT1()  asm volatile("cp.async.wait_group 1;" ::: "memory")
#define CP_WAIT0()  asm volatile("cp.async.wait_group 0;" ::: "memory")

// swizzled byte offset: row stride 128B, unit = 16B (8 halves)
#define SWZ(r, u) (((((uint32_t)(r)) << 3) + (((uint32_t)(u)) ^ (((uint32_t)(r)) & 7))) << 4)

// ---------------------------------------------------------------------------
// fp16 GEMM (m16n8k16 HMMA + cp.async + ldmatrix), unchanged.
// ---------------------------------------------------------------------------
#define KT       64
#define NCH      (768/KT)      // 12
#define STG_BYT  32768
#define GEMM_SMEM (3 * STG_BYT)   // 98304

__global__ __launch_bounds__(256, 2)
void gemm_h(const __half* __restrict__ A, const __half* __restrict__ Bt,
            void* __restrict__ Cout, int N,
            const float* __restrict__ bias,
            const float* __restrict__ scale,
            const float* __restrict__ shift,
            int half_out, __half* __restrict__ VT)
{
    extern __shared__ char smem[];
    const uint32_t sb = smem_u32(smem);
    const int tid  = threadIdx.x;
    const int lane = tid & 31;
    const int warp = tid >> 5;
    const int g = lane >> 2;
    const int q = lane & 3;
    const int wm0 = (warp >> 2) * 64;
    const int wn0 = (warp & 3) * 32;
    const int m0 = blockIdx.y * 128;
    const int n0 = blockIdx.x * 128;

    float acc[4][4][4];
#pragma unroll
    for (int mf = 0; mf < 4; mf++)
#pragma unroll
        for (int nf = 0; nf < 4; nf++)
#pragma unroll
            for (int cc = 0; cc < 4; cc++) acc[mf][nf][cc] = 0.f;

    const int r_ld = tid >> 3;
    const int u_ld = tid & 7;
    const int rowA_l = lane & 15;
    const int rowB_l = lane & 7;
    const int selA = lane >> 4;
    const int selB = lane >> 3;

#define LOAD_STAGE(s, kc) do { \
    uint32_t ab = sb + (s) * STG_BYT; \
    uint32_t bb = ab + 16384; \
    _Pragma("unroll") \
    for (int i = 0; i < 4; i++) { \
        int r = r_ld + i * 32; \
        uint32_t off = SWZ(r, u_ld); \
        cp16(ab + off, A  + (size_t)(m0 + r) * 768 + (kc) * KT + u_ld * 8); \
        cp16(bb + off, Bt + (size_t)(n0 + r) * 768 + (kc) * KT + u_ld * 8); \
    } \
} while (0)

    LOAD_STAGE(0, 0); CP_COMMIT();
    LOAD_STAGE(1, 1); CP_COMMIT();

    for (int kc = 0; kc < NCH; kc++) {
        if (kc == NCH - 1) { CP_WAIT0(); } else { CP_WAIT1(); }
        __syncthreads();
        if (kc + 2 < NCH) {
            LOAD_STAGE((kc + 2) % 3, kc + 2);
            CP_COMMIT();
        }
        const uint32_t ab = sb + (kc % 3) * STG_BYT;
        const uint32_t bb = ab + 16384;

#pragma unroll
        for (int ksp = 0; ksp < 2; ksp++) {
            uint32_t bf[4][4];
#pragma unroll
            for (int nf = 0; nf < 4; nf++) {
                int row = wn0 + nf * 8 + rowB_l;
                LDSM_X4(bf[nf][0], bf[nf][1], bf[nf][2], bf[nf][3],
                        bb + SWZ(row, 4 * ksp + selB));
            }
#pragma unroll
            for (int k2 = 0; k2 < 2; k2++) {
                uint32_t af[4][4];
#pragma unroll
                for (int mf = 0; mf < 4; mf++) {
                    int row = wm0 + mf * 16 + rowA_l;
                    LDSM_X4(af[mf][0], af[mf][1], af[mf][2], af[mf][3],
                            ab + SWZ(row, 4 * ksp + 2 * k2 + selA));
                }
#pragma unroll
                for (int mf = 0; mf < 4; mf++)
#pragma unroll
                    for (int nf = 0; nf < 4; nf++)
                        mma_f16(acc[mf][nf],
                                af[mf][0], af[mf][1], af[mf][2], af[mf][3],
                                bf[nf][2 * k2], bf[nf][2 * k2 + 1]);
            }
        }
    }

    const bool vtile = (VT != nullptr) && (n0 >= 2 * HID);

#pragma unroll
    for (int nf = 0; nf < 4; nf++) {
        int c = n0 + wn0 + nf * 8 + 2 * q;
        float2 sc = *(const float2*)(scale + c);
        float2 sh = *(const float2*)(shift + c);
        float2 bi = make_float2(0.f, 0.f);
        if (bias) bi = *(const float2*)(bias + c);
#pragma unroll
        for (int mf = 0; mf < 4; mf++) {
            int r = m0 + wm0 + mf * 16 + g;
            float v0 = (acc[mf][nf][0] + bi.x) * sc.x + sh.x;
            float v1 = (acc[mf][nf][1] + bi.y) * sc.y + sh.y;
            float v2 = (acc[mf][nf][2] + bi.x) * sc.x + sh.x;
            float v3 = (acc[mf][nf][3] + bi.y) * sc.y + sh.y;
            if (vtile) {
                int ch = c - 2 * HID;
                int h = ch >> 6, d = ch & 63;
                int bidx = r >> 10, s = r & 1023;
                __half* base = VT + (((size_t)bidx * NHEADS + h) << 16) + ((size_t)d << 10);
                base[s]            = __float2half_rn(v0);
                base[1024 + s]     = __float2half_rn(v1);
                base[s + 8]        = __float2half_rn(v2);
                base[1024 + s + 8] = __float2half_rn(v3);
            } else if (half_out) {
                __half* Ch = (__half*)Cout;
                *(__half2*)(Ch + (size_t)r * N + c) = __floats2half2_rn(v0, v1);
                *(__half2*)(Ch + (size_t)(r + 8) * N + c) = __floats2half2_rn(v2, v3);
            } else {
                float* Cf = (float*)Cout;
                *(float2*)(Cf + (size_t)r * N + c) = make_float2(v0, v1);
                *(float2*)(Cf + (size_t)(r + 8) * N + c) = make_float2(v2, v3);
            }
        }
    }
}

// ---------------------------------------------------------------------------
// merged prep kernel (x-round blocks do 4x work each)
// ---------------------------------------------------------------------------
#define NB_X4  (MTOT*HID/4/1024)                   // 1536 blocks, 4 float4/thread
#define NB_WQ  ((QKV_N/32) * (HID/32))             // 1728
#define NB_WO  ((HID/32) * (HID/32))               // 576
#define NB_SSF 9
#define NB_ALL (NB_X4 + NB_WQ + NB_WO + NB_SSF)
#define QPRE   0.18033688f                         // 0.125 * log2(e)

__global__ void prep_all(const float* __restrict__ x, __half* __restrict__ x_h,
                         const float* __restrict__ Wqkv, __half* __restrict__ wt_qkv,
                         const float* __restrict__ Wout, __half* __restrict__ wt_out,
                         const float* __restrict__ sc1, const float* __restrict__ sh1,
                         float* __restrict__ ssf)
{
    __shared__ float t[32][33];
    const int bid = blockIdx.x;
    const int tid = threadIdx.x;

    if (bid < NB_X4) {
        int base = bid * 1024 + tid;
#pragma unroll
        for (int it = 0; it < 4; it++) {
            int i = base + it * 256;
            float4 v = ((const float4*)x)[i];
            ((__half2*)x_h)[2 * i]     = __floats2half2_rn(v.x, v.y);
            ((__half2*)x_h)[2 * i + 1] = __floats2half2_rn(v.z, v.w);
        }
        return;
    }
    if (bid < NB_X4 + NB_WQ + NB_WO) {
        const float* in; __half* out; int R, C, idx;
        if (bid < NB_X4 + NB_WQ) {
            idx = bid - NB_X4; in = Wqkv; out = wt_qkv; R = HID; C = QKV_N;
        } else {
            idx = bid - NB_X4 - NB_WQ; in = Wout; out = wt_out; R = HID; C = HID;
        }
        int nbx = C / 32;
        int c0 = (idx % nbx) * 32, r0 = (idx / nbx) * 32;
        int tx = tid & 31, ty = tid >> 5;
#pragma unroll
        for (int i = 0; i < 32; i += 8)
            t[ty + i][tx] = in[(size_t)(r0 + ty + i) * C + c0 + tx];
        __syncthreads();
#pragma unroll
        for (int i = 0; i < 32; i += 8)
            out[(size_t)(c0 + ty + i) * R + r0 + tx] =
                __float2half_rn(t[tx][ty + i]);
        return;
    }
    {
        int i = (bid - (NB_X4 + NB_WQ + NB_WO)) * 256 + tid;
        if (i < QKV_N) {
            float f = (i < HID) ? QPRE : 1.0f;
            ssf[i]         = sc1[i] * f;
            ssf[QKV_N + i] = sh1[i] * f;
        }
    }
}

// ---------------------------------------------------------------------------
// fp16 flash attention, fixed-max exp2 softmax in fp16 (h2exp2), l via MMA.
// V stage tiles carry 8 extra constant rows (row 64 = 1.0) so the 9th PV
// output fragment accumulates the softmax denominator on the tensor pipe.
// 256 threads (8 warps), 128 q-rows/block, KV tiles of 64.
// smem: Q 16KB + 2x K 8KB + 2x V 9KB = 50.5KB.
// ---------------------------------------------------------------------------
#define ATT_VROWS 72
#define ATT_VSTG  (ATT_VROWS * 128)               // 9216
#define ATT_KB(s) (16384 + (s) * 8192)
#define ATT_VB(s) (32768 + (s) * ATT_VSTG)
#define ATTN_SMEM (32768 + 2 * ATT_VSTG)          // 51200

__global__ __launch_bounds__(256, 2)
void attn_h(const __half* __restrict__ qkv, const __half* __restrict__ vt,
            __half* __restrict__ out)
{
    extern __shared__ char sm[];
    const uint32_t sb = smem_u32(sm);

    const int tid  = threadIdx.x;
    const int lane = tid & 31;
    const int warp = tid >> 5;     // 0..7
    const int g = lane >> 2;
    const int q = lane & 3;
    const int s0 = blockIdx.x * 128;
    const int bh = blockIdx.y;
    const int b = bh / NHEADS;
    const int h = bh - b * NHEADS;

    const __half* qbase = qkv + (size_t)b * SEQ * QKV_N + h * HDIM;
    const __half* kbase = qbase + HID;
    const __half* vtb   = vt + ((size_t)bh << 16);

    const int r_ld = tid >> 3;   // 0..31
    const int u_ld = tid & 7;    // 0..7

#define LOAD_KV(t_, s_) do { \
    int j0_ = (t_) * 64; \
    _Pragma("unroll") \
    for (int i = 0; i < 2; i++) { \
        int r = r_ld + i * 32; \
        cp16(sb + ATT_KB(s_) + SWZ(r, u_ld), kbase + (size_t)(j0_ + r) * QKV_N + u_ld * 8); \
        cp16(sb + ATT_VB(s_) + SWZ(r, u_ld), vtb + ((size_t)r << 10) + j0_ + u_ld * 8); \
    } \
} while (0)

    // prologue: Q tile (128 rows) + KV tile 0
#pragma unroll
    for (int i = 0; i < 4; i++) {
        int r = r_ld + i * 32;
        cp16(sb + SWZ(r, u_ld), qbase + (size_t)(s0 + r) * QKV_N + u_ld * 8);
    }
    LOAD_KV(0, 0);
    CP_COMMIT();

    // constant rows 64..71 of both V stages: row 64 = ones (denominator row)
    if (tid < 128) {
        int st = tid >> 6;             // stage 0/1
        int r  = 64 + ((tid >> 3) & 7);
        int u  = tid & 7;
        uint32_t w = (r == 64) ? 0x3C003C00u : 0u;   // half2(1,1) : 0
        uint4 v; v.x = v.y = v.z = v.w = w;
        *(uint4*)(sm + ATT_VB(st) + SWZ(r, u)) = v;
    }

    float o_acc[9][4];
#pragma unroll
    for (int nf = 0; nf < 9; nf++)
#pragma unroll
        for (int cc = 0; cc < 4; cc++) o_acc[nf][cc] = 0.f;

    const int qrow = warp * 16 + (lane & 15);
    const int qsel = lane >> 4;
    const int kfrow_l = lane & 7;
    const int kfsel = lane >> 3;

    for (int t = 0; t < SEQ / 64; t++) {
        CP_WAIT0();
        __syncthreads();   // (t=0: also publishes the ones-rows block-wide)
        if (t + 1 < SEQ / 64) {
            LOAD_KV(t + 1, (t + 1) & 1);
            CP_COMMIT();
        }
        const uint32_t kb_base = sb + ATT_KB(t & 1);
        const uint32_t vb_base = sb + ATT_VB(t & 1);

        // S = Q K^T  (log2-domain scores: Q pre-scaled by 0.125*log2e)
        float s[8][4];
#pragma unroll
        for (int nf = 0; nf < 8; nf++)
#pragma unroll
            for (int cc = 0; cc < 4; cc++) s[nf][cc] = 0.f;

#pragma unroll
        for (int ksp = 0; ksp < 2; ksp++) {
            uint32_t qa0[4], qa1[4];
            LDSM_X4(qa0[0], qa0[1], qa0[2], qa0[3], sb + SWZ(qrow, 4 * ksp + qsel));
            LDSM_X4(qa1[0], qa1[1], qa1[2], qa1[3], sb + SWZ(qrow, 4 * ksp + 2 + qsel));
#pragma unroll
            for (int nf = 0; nf < 8; nf++) {
                uint32_t kb[4];
                LDSM_X4(kb[0], kb[1], kb[2], kb[3],
                        kb_base + SWZ(nf * 8 + kfrow_l, 4 * ksp + kfsel));
                mma_f16(s[nf], qa0[0], qa0[1], qa0[2], qa0[3], kb[0], kb[1]);
                mma_f16(s[nf], qa1[0], qa1[1], qa1[2], qa1[3], kb[2], kb[3]);
            }
        }

        // p = exp2(s) computed in fp16x2: result IS the PV A-fragment
        uint32_t pa[8][2];   // [ks-pair rows][row g / g+8]
#pragma unroll
        for (int nf = 0; nf < 8; nf++) {
            pa[nf][0] = exp2_pack(s[nf][0], s[nf][1]);
            pa[nf][1] = exp2_pack(s[nf][2], s[nf][3]);
        }

        // O += P @ V (nf=8 fragment accumulates l via the ones row)
#pragma unroll
        for (int ksp = 0; ksp < 2; ksp++) {
#pragma unroll
            for (int k2 = 0; k2 < 2; k2++) {
                int ks = 2 * ksp + k2;
                uint32_t a0 = pa[2 * ks][0];
                uint32_t a1 = pa[2 * ks][1];
                uint32_t a2 = pa[2 * ks + 1][0];
                uint32_t a3 = pa[2 * ks + 1][1];
#pragma unroll
                for (int nf = 0; nf < 9; nf++) {
                    uint32_t vb[4];
                    LDSM_X4(vb[0], vb[1], vb[2], vb[3],
                            vb_base + SWZ(nf * 8 + kfrow_l, 4 * ksp + kfsel));
                    mma_f16(o_acc[nf], a0, a1, a2, a3, vb[2 * k2], vb[2 * k2 + 1]);
                }
            }
        }
    }

    // l lives in column 64 -> q=0 lane's c0 (row g) and c2 (row g+8)
    float l0 = __shfl_sync(0xffffffffu, o_acc[8][0], lane & ~3);
    float l1 = __shfl_sync(0xffffffffu, o_acc[8][2], lane & ~3);
    float inv0 = 1.0f / l0;
    float inv1 = 1.0f / l1;
    int r0 = b * SEQ + s0 + warp * 16 + g;
#pragma unroll
    for (int nf = 0; nf < 8; nf++) {
        int c = h * HDIM + nf * 8 + 2 * q;
        *(__half2*)(out + (size_t)r0 * HID + c) =
            __floats2half2_rn(o_acc[nf][0] * inv0, o_acc[nf][1] * inv0);
        *(__half2*)(out + (size_t)(r0 + 8) * HID + c) =
            __floats2half2_rn(o_acc[nf][2] * inv1, o_acc[nf][3] * inv1);
    }
}

// ---------------------------------------------------------------------------
extern "C" void kernel_launch(void* const* d_in, const int* in_sizes, int n_in,
                              void* d_out, int out_size)
{
    (void)in_sizes; (void)n_in; (void)out_size;
    const float* x      = (const float*)d_in[0];
    const float* Wqkv   = (const float*)d_in[1];
    const float* scale1 = (const float*)d_in[2];
    const float* shift1 = (const float*)d_in[3];
    const float* Wout   = (const float*)d_in[4];
    const float* bout   = (const float*)d_in[5];
    const float* scale2 = (const float*)d_in[6];
    const float* shift2 = (const float*)d_in[7];
    float* out = (float*)d_out;

    __half *x_h, *qkv_h, *vt_h, *o_h, *wt_qkv, *wt_out;
    float* ssf;
    cudaGetSymbolAddress((void**)&x_h, g_x);
    cudaGetSymbolAddress((void**)&qkv_h, g_qkv);
    cudaGetSymbolAddress((void**)&vt_h, g_vt);
    cudaGetSymbolAddress((void**)&o_h, g_o);
    cudaGetSymbolAddress((void**)&wt_qkv, g_wt_qkv);
    cudaGetSymbolAddress((void**)&wt_out, g_wt_out);
    cudaGetSymbolAddress((void**)&ssf, g_ssf);

    static bool attr_set = false;
    if (!attr_set) {
        cudaFuncSetAttribute(gemm_h, cudaFuncAttributeMaxDynamicSharedMemorySize, GEMM_SMEM);
        cudaFuncSetAttribute(attn_h, cudaFuncAttributeMaxDynamicSharedMemorySize, ATTN_SMEM);
        attr_set = true;
    }

    // 0) merged prep
    prep_all<<<NB_ALL, 256>>>(x, x_h, Wqkv, wt_qkv, Wout, wt_out,
                              scale1, shift1, ssf);
    // 1) QKV projection + SSF affine (fp16 out; V written transposed)
    gemm_h<<<dim3(QKV_N / 128, MTOT / 128), 256, GEMM_SMEM>>>(
        x_h, wt_qkv, qkv_h, QKV_N, nullptr, ssf, ssf + QKV_N, 1, vt_h);
    // 2) attention
    attn_h<<<dim3(SEQ / 128, BATCH * NHEADS), 256, ATTN_SMEM>>>(qkv_h, vt_h, o_h);
    // 3) out projection + bias + SSF affine (fp32 exact epilogue)
    gemm_h<<<dim3(HID / 128, MTOT / 128), 256, GEMM_SMEM>>>(
        o_h, wt_out, out, HID, bout, scale2, shift2, 0, nullptr);
}

// round 11
// speedup vs baseline: 1.0059x; 1.0059x over previous
#include <cuda_runtime.h>
#include <cuda_fp16.h>
#include <math.h>
#include <stdint.h>

#define BATCH   8
#define SEQ     1024
#define HID     768
#define NHEADS  12
#define HDIM    64
#define QKV_N   (3*HID)          // 2304
#define MTOT    (BATCH*SEQ)      // 8192

__device__ __half g_x[(size_t)MTOT * HID];        // fp16-rounded x
__device__ __half g_qkv[(size_t)MTOT * QKV_N];    // Q,K channels used
__device__ __half g_vt[(size_t)BATCH * NHEADS * HDIM * SEQ];  // V^T [bh][d][s]
__device__ __half g_o[(size_t)MTOT * HID];        // attention out
__device__ __half g_wt_qkv[(size_t)QKV_N * HID];  // Wqkv^T fp16
__device__ __half g_wt_out[(size_t)HID * HID];    // Wout^T fp16
__device__ float  g_ssf[2 * QKV_N];               // Q-prescaled scale1/shift1

// ---------------------------------------------------------------------------
// helpers
// ---------------------------------------------------------------------------
__device__ __forceinline__ uint32_t smem_u32(const void* p) {
    uint32_t a;
    asm("{ .reg .u64 t; cvta.to.shared.u64 t, %1; cvt.u32.u64 %0, t; }" : "=r"(a) : "l"(p));
    return a;
}
__device__ __forceinline__ uint32_t exp2_pack(float lo, float hi) {
    __half2 h = h2exp2(__floats2half2_rn(lo, hi));
    return *reinterpret_cast<uint32_t*>(&h);
}
__device__ __forceinline__ void mma_f16(float* c,
                                        uint32_t a0, uint32_t a1, uint32_t a2, uint32_t a3,
                                        uint32_t b0, uint32_t b1) {
    asm volatile(
        "mma.sync.aligned.m16n8k16.row.col.f32.f16.f16.f32 "
        "{%0,%1,%2,%3}, {%4,%5,%6,%7}, {%8,%9}, {%0,%1,%2,%3};"
        : "+f"(c[0]), "+f"(c[1]), "+f"(c[2]), "+f"(c[3])
        : "r"(a0), "r"(a1), "r"(a2), "r"(a3), "r"(b0), "r"(b1));
}
#define LDSM_X4(r0, r1, r2, r3, addr) \
    asm volatile("ldmatrix.sync.aligned.m8n8.x4.shared.b16 {%0,%1,%2,%3}, [%4];" \
        : "=r"(r0), "=r"(r1), "=r"(r2), "=r"(r3) : "r"(addr))
__device__ __forceinline__ void cp16(uint32_t dst, const void* src) {
    asm volatile("cp.async.cg.shared.global [%0], [%1], 16;" :: "r"(dst), "l"(src));
}
#define CP_COMMIT() asm volatile("cp.async.commit_group;" ::: "memory")
#define CP_WAIT1()  asm volatile("cp.async.wait_group 1;" ::: "memory")
#define CP_WAIT0()  asm volatile("cp.async.wait_group 0;" ::: "memory")

// swizzled byte offset: row stride 128B, unit = 16B (8 halves)
#define SWZ(r, u) (((((uint32_t)(r)) << 3) + (((uint32_t)(u)) ^ (((uint32_t)(r)) & 7))) << 4)

// ---------------------------------------------------------------------------
// fp16 GEMM (m16n8k16 HMMA + cp.async + ldmatrix), unchanged.
// ---------------------------------------------------------------------------
#define KT       64
#define NCH      (768/KT)      // 12
#define STG_BYT  32768
#define GEMM_SMEM (3 * STG_BYT)   // 98304

__global__ __launch_bounds__(256, 2)
void gemm_h(const __half* __restrict__ A, const __half* __restrict__ Bt,
            void* __restrict__ Cout, int N,
            const float* __restrict__ bias,
            const float* __restrict__ scale,
            const float* __restrict__ shift,
            int half_out, __half* __restrict__ VT)
{
    extern __shared__ char smem[];
    const uint32_t sb = smem_u32(smem);
    const int tid  = threadIdx.x;
    const int lane = tid & 31;
    const int warp = tid >> 5;
    const int g = lane >> 2;
    const int q = lane & 3;
    const int wm0 = (warp >> 2) * 64;
    const int wn0 = (warp & 3) * 32;
    const int m0 = blockIdx.y * 128;
    const int n0 = blockIdx.x * 128;

    float acc[4][4][4];
#pragma unroll
    for (int mf = 0; mf < 4; mf++)
#pragma unroll
        for (int nf = 0; nf < 4; nf++)
#pragma unroll
            for (int cc = 0; cc < 4; cc++) acc[mf][nf][cc] = 0.f;

    const int r_ld = tid >> 3;
    const int u_ld = tid & 7;
    const int rowA_l = lane & 15;
    const int rowB_l = lane & 7;
    const int selA = lane >> 4;
    const int selB = lane >> 3;

#define LOAD_STAGE(s, kc) do { \
    uint32_t ab = sb + (s) * STG_BYT; \
    uint32_t bb = ab + 16384; \
    _Pragma("unroll") \
    for (int i = 0; i < 4; i++) { \
        int r = r_ld + i * 32; \
        uint32_t off = SWZ(r, u_ld); \
        cp16(ab + off, A  + (size_t)(m0 + r) * 768 + (kc) * KT + u_ld * 8); \
        cp16(bb + off, Bt + (size_t)(n0 + r) * 768 + (kc) * KT + u_ld * 8); \
    } \
} while (0)

    LOAD_STAGE(0, 0); CP_COMMIT();
    LOAD_STAGE(1, 1); CP_COMMIT();

    for (int kc = 0; kc < NCH; kc++) {
        if (kc == NCH - 1) { CP_WAIT0(); } else { CP_WAIT1(); }
        __syncthreads();
        if (kc + 2 < NCH) {
            LOAD_STAGE((kc + 2) % 3, kc + 2);
            CP_COMMIT();
        }
        const uint32_t ab = sb + (kc % 3) * STG_BYT;
        const uint32_t bb = ab + 16384;

#pragma unroll
        for (int ksp = 0; ksp < 2; ksp++) {
            uint32_t bf[4][4];
#pragma unroll
            for (int nf = 0; nf < 4; nf++) {
                int row = wn0 + nf * 8 + rowB_l;
                LDSM_X4(bf[nf][0], bf[nf][1], bf[nf][2], bf[nf][3],
                        bb + SWZ(row, 4 * ksp + selB));
            }
#pragma unroll
            for (int k2 = 0; k2 < 2; k2++) {
                uint32_t af[4][4];
#pragma unroll
                for (int mf = 0; mf < 4; mf++) {
                    int row = wm0 + mf * 16 + rowA_l;
                    LDSM_X4(af[mf][0], af[mf][1], af[mf][2], af[mf][3],
                            ab + SWZ(row, 4 * ksp + 2 * k2 + selA));
                }
#pragma unroll
                for (int mf = 0; mf < 4; mf++)
#pragma unroll
                    for (int nf = 0; nf < 4; nf++)
                        mma_f16(acc[mf][nf],
                                af[mf][0], af[mf][1], af[mf][2], af[mf][3],
                                bf[nf][2 * k2], bf[nf][2 * k2 + 1]);
            }
        }
    }

    const bool vtile = (VT != nullptr) && (n0 >= 2 * HID);

#pragma unroll
    for (int nf = 0; nf < 4; nf++) {
        int c = n0 + wn0 + nf * 8 + 2 * q;
        float2 sc = *(const float2*)(scale + c);
        float2 sh = *(const float2*)(shift + c);
        float2 bi = make_float2(0.f, 0.f);
        if (bias) bi = *(const float2*)(bias + c);
#pragma unroll
        for (int mf = 0; mf < 4; mf++) {
            int r = m0 + wm0 + mf * 16 + g;
            float v0 = (acc[mf][nf][0] + bi.x) * sc.x + sh.x;
            float v1 = (acc[mf][nf][1] + bi.y) * sc.y + sh.y;
            float v2 = (acc[mf][nf][2] + bi.x) * sc.x + sh.x;
            float v3 = (acc[mf][nf][3] + bi.y) * sc.y + sh.y;
            if (vtile) {
                int ch = c - 2 * HID;
                int h = ch >> 6, d = ch & 63;
                int bidx = r >> 10, s = r & 1023;
                __half* base = VT + (((size_t)bidx * NHEADS + h) << 16) + ((size_t)d << 10);
                base[s]            = __float2half_rn(v0);
                base[1024 + s]     = __float2half_rn(v1);
                base[s + 8]        = __float2half_rn(v2);
                base[1024 + s + 8] = __float2half_rn(v3);
            } else if (half_out) {
                __half* Ch = (__half*)Cout;
                *(__half2*)(Ch + (size_t)r * N + c) = __floats2half2_rn(v0, v1);
                *(__half2*)(Ch + (size_t)(r + 8) * N + c) = __floats2half2_rn(v2, v3);
            } else {
                float* Cf = (float*)Cout;
                *(float2*)(Cf + (size_t)r * N + c) = make_float2(v0, v1);
                *(float2*)(Cf + (size_t)(r + 8) * N + c) = make_float2(v2, v3);
            }
        }
    }
}

// ---------------------------------------------------------------------------
// merged prep kernel (x-round blocks do 4x work each)
// ---------------------------------------------------------------------------
#define NB_X4  (MTOT*HID/4/1024)                   // 1536 blocks
#define NB_WQ  ((QKV_N/32) * (HID/32))             // 1728
#define NB_WO  ((HID/32) * (HID/32))               // 576
#define NB_SSF 9
#define NB_ALL (NB_X4 + NB_WQ + NB_WO + NB_SSF)
#define QPRE   0.18033688f                         // 0.125 * log2(e)

__global__ void prep_all(const float* __restrict__ x, __half* __restrict__ x_h,
                         const float* __restrict__ Wqkv, __half* __restrict__ wt_qkv,
                         const float* __restrict__ Wout, __half* __restrict__ wt_out,
                         const float* __restrict__ sc1, const float* __restrict__ sh1,
                         float* __restrict__ ssf)
{
    __shared__ float t[32][33];
    const int bid = blockIdx.x;
    const int tid = threadIdx.x;

    if (bid < NB_X4) {
        int base = bid * 1024 + tid;
#pragma unroll
        for (int it = 0; it < 4; it++) {
            int i = base + it * 256;
            float4 v = ((const float4*)x)[i];
            ((__half2*)x_h)[2 * i]     = __floats2half2_rn(v.x, v.y);
            ((__half2*)x_h)[2 * i + 1] = __floats2half2_rn(v.z, v.w);
        }
        return;
    }
    if (bid < NB_X4 + NB_WQ + NB_WO) {
        const float* in; __half* out; int R, C, idx;
        if (bid < NB_X4 + NB_WQ) {
            idx = bid - NB_X4; in = Wqkv; out = wt_qkv; R = HID; C = QKV_N;
        } else {
            idx = bid - NB_X4 - NB_WQ; in = Wout; out = wt_out; R = HID; C = HID;
        }
        int nbx = C / 32;
        int c0 = (idx % nbx) * 32, r0 = (idx / nbx) * 32;
        int tx = tid & 31, ty = tid >> 5;
#pragma unroll
        for (int i = 0; i < 32; i += 8)
            t[ty + i][tx] = in[(size_t)(r0 + ty + i) * C + c0 + tx];
        __syncthreads();
#pragma unroll
        for (int i = 0; i < 32; i += 8)
            out[(size_t)(c0 + ty + i) * R + r0 + tx] =
                __float2half_rn(t[tx][ty + i]);
        return;
    }
    {
        int i = (bid - (NB_X4 + NB_WQ + NB_WO)) * 256 + tid;
        if (i < QKV_N) {
            float f = (i < HID) ? QPRE : 1.0f;
            ssf[i]         = sc1[i] * f;
            ssf[QKV_N + i] = sh1[i] * f;
        }
    }
}

// ---------------------------------------------------------------------------
// fp16 flash attention, fixed-max exp2 softmax in fp16 (h2exp2), l via MMA.
// V stage tiles carry 8 extra constant rows (row 64 = 1.0) so the 9th PV
// output fragment accumulates the softmax denominator on the tensor pipe.
// V fragments hoisted per ksp: vb[9][4] via 9 LDSM_X4, fully consumed.
// 256 threads (8 warps), 128 q-rows/block, KV tiles of 64.
// ---------------------------------------------------------------------------
#define ATT_VROWS 72
#define ATT_VSTG  (ATT_VROWS * 128)               // 9216
#define ATT_KB(s) (16384 + (s) * 8192)
#define ATT_VB(s) (32768 + (s) * ATT_VSTG)
#define ATTN_SMEM (32768 + 2 * ATT_VSTG)          // 51200

__global__ __launch_bounds__(256, 2)
void attn_h(const __half* __restrict__ qkv, const __half* __restrict__ vt,
            __half* __restrict__ out)
{
    extern __shared__ char sm[];
    const uint32_t sb = smem_u32(sm);

    const int tid  = threadIdx.x;
    const int lane = tid & 31;
    const int warp = tid >> 5;     // 0..7
    const int g = lane >> 2;
    const int q = lane & 3;
    const int s0 = blockIdx.x * 128;
    const int bh = blockIdx.y;
    const int b = bh / NHEADS;
    const int h = bh - b * NHEADS;

    const __half* qbase = qkv + (size_t)b * SEQ * QKV_N + h * HDIM;
    const __half* kbase = qbase + HID;
    const __half* vtb   = vt + ((size_t)bh << 16);

    const int r_ld = tid >> 3;   // 0..31
    const int u_ld = tid & 7;    // 0..7

#define LOAD_KV(t_, s_) do { \
    int j0_ = (t_) * 64; \
    _Pragma("unroll") \
    for (int i = 0; i < 2; i++) { \
        int r = r_ld + i * 32; \
        cp16(sb + ATT_KB(s_) + SWZ(r, u_ld), kbase + (size_t)(j0_ + r) * QKV_N + u_ld * 8); \
        cp16(sb + ATT_VB(s_) + SWZ(r, u_ld), vtb + ((size_t)r << 10) + j0_ + u_ld * 8); \
    } \
} while (0)

    // prologue: Q tile (128 rows) + KV tile 0
#pragma unroll
    for (int i = 0; i < 4; i++) {
        int r = r_ld + i * 32;
        cp16(sb + SWZ(r, u_ld), qbase + (size_t)(s0 + r) * QKV_N + u_ld * 8);
    }
    LOAD_KV(0, 0);
    CP_COMMIT();

    // constant rows 64..71 of both V stages: row 64 = ones (denominator row)
    if (tid < 128) {
        int st = tid >> 6;             // stage 0/1
        int r  = 64 + ((tid >> 3) & 7);
        int u  = tid & 7;
        uint32_t w = (r == 64) ? 0x3C003C00u : 0u;   // half2(1,1) : 0
        uint4 v; v.x = v.y = v.z = v.w = w;
        *(uint4*)(sm + ATT_VB(st) + SWZ(r, u)) = v;
    }

    float o_acc[9][4];
#pragma unroll
    for (int nf = 0; nf < 9; nf++)
#pragma unroll
        for (int cc = 0; cc < 4; cc++) o_acc[nf][cc] = 0.f;

    const int qrow = warp * 16 + (lane & 15);
    const int qsel = lane >> 4;
    const int kfrow_l = lane & 7;
    const int kfsel = lane >> 3;

    for (int t = 0; t < SEQ / 64; t++) {
        CP_WAIT0();
        __syncthreads();   // (t=0: also publishes the ones-rows block-wide)
        if (t + 1 < SEQ / 64) {
            LOAD_KV(t + 1, (t + 1) & 1);
            CP_COMMIT();
        }
        const uint32_t kb_base = sb + ATT_KB(t & 1);
        const uint32_t vb_base = sb + ATT_VB(t & 1);

        // S = Q K^T  (log2-domain scores: Q pre-scaled by 0.125*log2e)
        float s[8][4];
#pragma unroll
        for (int nf = 0; nf < 8; nf++)
#pragma unroll
            for (int cc = 0; cc < 4; cc++) s[nf][cc] = 0.f;

#pragma unroll
        for (int ksp = 0; ksp < 2; ksp++) {
            uint32_t qa0[4], qa1[4];
            LDSM_X4(qa0[0], qa0[1], qa0[2], qa0[3], sb + SWZ(qrow, 4 * ksp + qsel));
            LDSM_X4(qa1[0], qa1[1], qa1[2], qa1[3], sb + SWZ(qrow, 4 * ksp + 2 + qsel));
#pragma unroll
            for (int nf = 0; nf < 8; nf++) {
                uint32_t kb[4];
                LDSM_X4(kb[0], kb[1], kb[2], kb[3],
                        kb_base + SWZ(nf * 8 + kfrow_l, 4 * ksp + kfsel));
                mma_f16(s[nf], qa0[0], qa0[1], qa0[2], qa0[3], kb[0], kb[1]);
                mma_f16(s[nf], qa1[0], qa1[1], qa1[2], qa1[3], kb[2], kb[3]);
            }
        }

        // p = exp2(s) in fp16x2: result IS the PV A-fragment
        uint32_t pa[8][2];
#pragma unroll
        for (int nf = 0; nf < 8; nf++) {
            pa[nf][0] = exp2_pack(s[nf][0], s[nf][1]);
            pa[nf][1] = exp2_pack(s[nf][2], s[nf][3]);
        }

        // O += P @ V ; V frags hoisted per ksp (fully used across both k2)
#pragma unroll
        for (int ksp = 0; ksp < 2; ksp++) {
            uint32_t vb[9][4];
#pragma unroll
            for (int nf = 0; nf < 9; nf++)
                LDSM_X4(vb[nf][0], vb[nf][1], vb[nf][2], vb[nf][3],
                        vb_base + SWZ(nf * 8 + kfrow_l, 4 * ksp + kfsel));
#pragma unroll
            for (int k2 = 0; k2 < 2; k2++) {
                int ks = 2 * ksp + k2;
                uint32_t a0 = pa[2 * ks][0];
                uint32_t a1 = pa[2 * ks][1];
                uint32_t a2 = pa[2 * ks + 1][0];
                uint32_t a3 = pa[2 * ks + 1][1];
#pragma unroll
                for (int nf = 0; nf < 9; nf++)
                    mma_f16(o_acc[nf], a0, a1, a2, a3,
                            vb[nf][2 * k2], vb[nf][2 * k2 + 1]);
            }
        }
    }

    // l lives in column 64 -> q=0 lane's c0 (row g) and c2 (row g+8)
    float l0 = __shfl_sync(0xffffffffu, o_acc[8][0], lane & ~3);
    float l1 = __shfl_sync(0xffffffffu, o_acc[8][2], lane & ~3);
    float inv0 = 1.0f / l0;
    float inv1 = 1.0f / l1;
    int r0 = b * SEQ + s0 + warp * 16 + g;
#pragma unroll
    for (int nf = 0; nf < 8; nf++) {
        int c = h * HDIM + nf * 8 + 2 * q;
        *(__half2*)(out + (size_t)r0 * HID + c) =
            __floats2half2_rn(o_acc[nf][0] * inv0, o_acc[nf][1] * inv0);
        *(__half2*)(out + (size_t)(r0 + 8) * HID + c) =
            __floats2half2_rn(o_acc[nf][2] * inv1, o_acc[nf][3] * inv1);
    }
}

// ---------------------------------------------------------------------------
extern "C" void kernel_launch(void* const* d_in, const int* in_sizes, int n_in,
                              void* d_out, int out_size)
{
    (void)in_sizes; (void)n_in; (void)out_size;
    const float* x      = (const float*)d_in[0];
    const float* Wqkv   = (const float*)d_in[1];
    const float* scale1 = (const float*)d_in[2];
    const float* shift1 = (const float*)d_in[3];
    const float* Wout   = (const float*)d_in[4];
    const float* bout   = (const float*)d_in[5];
    const float* scale2 = (const float*)d_in[6];
    const float* shift2 = (const float*)d_in[7];
    float* out = (float*)d_out;

    __half *x_h, *qkv_h, *vt_h, *o_h, *wt_qkv, *wt_out;
    float* ssf;
    cudaGetSymbolAddress((void**)&x_h, g_x);
    cudaGetSymbolAddress((void**)&qkv_h, g_qkv);
    cudaGetSymbolAddress((void**)&vt_h, g_vt);
    cudaGetSymbolAddress((void**)&o_h, g_o);
    cudaGetSymbolAddress((void**)&wt_qkv, g_wt_qkv);
    cudaGetSymbolAddress((void**)&wt_out, g_wt_out);
    cudaGetSymbolAddress((void**)&ssf, g_ssf);

    static bool attr_set = false;
    if (!attr_set) {
        cudaFuncSetAttribute(gemm_h, cudaFuncAttributeMaxDynamicSharedMemorySize, GEMM_SMEM);
        cudaFuncSetAttribute(attn_h, cudaFuncAttributeMaxDynamicSharedMemorySize, ATTN_SMEM);
        attr_set = true;
    }

    // 0) merged prep
    prep_all<<<NB_ALL, 256>>>(x, x_h, Wqkv, wt_qkv, Wout, wt_out,
                              scale1, shift1, ssf);
    // 1) QKV projection + SSF affine (fp16 out; V written transposed)
    gemm_h<<<dim3(QKV_N / 128, MTOT / 128), 256, GEMM_SMEM>>>(
        x_h, wt_qkv, qkv_h, QKV_N, nullptr, ssf, ssf + QKV_N, 1, vt_h);
    // 2) attention
    attn_h<<<dim3(SEQ / 128, BATCH * NHEADS), 256, ATTN_SMEM>>>(qkv_h, vt_h, o_h);
    // 3) out projection + bias + SSF affine (fp32 exact epilogue)
    gemm_h<<<dim3(HID / 128, MTOT / 128), 256, GEMM_SMEM>>>(
        o_h, wt_out, out, HID, bout, scale2, shift2, 0, nullptr);
}

// round 12
// speedup vs baseline: 1.0083x; 1.0024x over previous
#include <cuda_runtime.h>
#include <cuda_fp16.h>
#include <math.h>
#include <stdint.h>

#define BATCH   8
#define SEQ     1024
#define HID     768
#define NHEADS  12
#define HDIM    64
#define QKV_N   (3*HID)          // 2304
#define MTOT    (BATCH*SEQ)      // 8192

__device__ __half g_x[(size_t)MTOT * HID];
__device__ __half g_qkv[(size_t)MTOT * QKV_N];
__device__ __half g_vt[(size_t)BATCH * NHEADS * HDIM * SEQ];  // V^T [bh][d][s]
__device__ __half g_o[(size_t)MTOT * HID];
__device__ __half g_wt_qkv[(size_t)QKV_N * HID];
__device__ __half g_wt_out[(size_t)HID * HID];
__device__ float  g_ssf[2 * QKV_N];

// ---------------------------------------------------------------------------
// helpers
// ---------------------------------------------------------------------------
__device__ __forceinline__ uint32_t smem_u32(const void* p) {
    uint32_t a;
    asm("{ .reg .u64 t; cvta.to.shared.u64 t, %1; cvt.u32.u64 %0, t; }" : "=r"(a) : "l"(p));
    return a;
}
__device__ __forceinline__ uint32_t packh2(float lo, float hi) {
    __half2 h = __floats2half2_rn(lo, hi);
    return *reinterpret_cast<uint32_t*>(&h);
}
__device__ __forceinline__ void mma_f16(float* c,
                                        uint32_t a0, uint32_t a1, uint32_t a2, uint32_t a3,
                                        uint32_t b0, uint32_t b1) {
    asm volatile(
        "mma.sync.aligned.m16n8k16.row.col.f32.f16.f16.f32 "
        "{%0,%1,%2,%3}, {%4,%5,%6,%7}, {%8,%9}, {%0,%1,%2,%3};"
        : "+f"(c[0]), "+f"(c[1]), "+f"(c[2]), "+f"(c[3])
        : "r"(a0), "r"(a1), "r"(a2), "r"(a3), "r"(b0), "r"(b1));
}
#define LDSM_X4(r0, r1, r2, r3, addr) \
    asm volatile("ldmatrix.sync.aligned.m8n8.x4.shared.b16 {%0,%1,%2,%3}, [%4];" \
        : "=r"(r0), "=r"(r1), "=r"(r2), "=r"(r3) : "r"(addr))
__device__ __forceinline__ void cp16(uint32_t dst, const void* src) {
    asm volatile("cp.async.cg.shared.global [%0], [%1], 16;" :: "r"(dst), "l"(src));
}
#define CP_COMMIT() asm volatile("cp.async.commit_group;" ::: "memory")
#define CP_WAIT1()  asm volatile("cp.async.wait_group 1;" ::: "memory")
#define CP_WAIT0()  asm volatile("cp.async.wait_group 0;" ::: "memory")

#define SWZ(r, u) (((((uint32_t)(r)) << 3) + (((uint32_t)(u)) ^ (((uint32_t)(r)) & 7))) << 4)

// ---------------------------------------------------------------------------
// BIG fp16 GEMM: 128x256 block tile, 8 warps x (64x64), 1 CTA/SM, 3 stages.
// Used for the QKV projection (fp16 out, V transposed to VT).
// ---------------------------------------------------------------------------
#define BKT       64
#define BNCH      (768/BKT)        // 12
#define BSTG      49152            // A 16KB + B 32KB
#define BGEMM_SMEM (3 * BSTG)      // 147456

__global__ __launch_bounds__(256, 1)
void gemm_big(const __half* __restrict__ A, const __half* __restrict__ Bt,
              __half* __restrict__ Cout, int N,
              const float* __restrict__ scale,
              const float* __restrict__ shift,
              __half* __restrict__ VT)
{
    extern __shared__ char smem[];
    const uint32_t sb = smem_u32(smem);
    const int tid  = threadIdx.x;
    const int lane = tid & 31;
    const int warp = tid >> 5;
    const int g = lane >> 2;
    const int q = lane & 3;
    const int wm0 = (warp >> 2) * 64;   // 0 / 64
    const int wn0 = (warp & 3) * 64;    // 0,64,128,192
    const int m0 = blockIdx.y * 128;
    const int n0 = blockIdx.x * 256;

    float acc[4][8][4];
#pragma unroll
    for (int mf = 0; mf < 4; mf++)
#pragma unroll
        for (int nf = 0; nf < 8; nf++)
#pragma unroll
            for (int cc = 0; cc < 4; cc++) acc[mf][nf][cc] = 0.f;

    const int r_ld = tid >> 3;     // 0..31
    const int u_ld = tid & 7;      // 0..7
    const int rowA_l = lane & 15;
    const int rowB_l = lane & 7;
    const int selA = lane >> 4;
    const int selB = lane >> 3;

#define BLOAD_STAGE(s, kc) do { \
    uint32_t ab = sb + (s) * BSTG; \
    uint32_t bb = ab + 16384; \
    _Pragma("unroll") \
    for (int i = 0; i < 4; i++) { \
        int r = r_ld + i * 32; \
        cp16(ab + SWZ(r, u_ld), A + (size_t)(m0 + r) * 768 + (kc) * BKT + u_ld * 8); \
    } \
    _Pragma("unroll") \
    for (int i = 0; i < 8; i++) { \
        int r = r_ld + i * 32; \
        cp16(bb + SWZ(r, u_ld), Bt + (size_t)(n0 + r) * 768 + (kc) * BKT + u_ld * 8); \
    } \
} while (0)

    BLOAD_STAGE(0, 0); CP_COMMIT();
    BLOAD_STAGE(1, 1); CP_COMMIT();

    for (int kc = 0; kc < BNCH; kc++) {
        if (kc == BNCH - 1) { CP_WAIT0(); } else { CP_WAIT1(); }
        __syncthreads();
        if (kc + 2 < BNCH) {
            BLOAD_STAGE((kc + 2) % 3, kc + 2);
            CP_COMMIT();
        }
        const uint32_t ab = sb + (kc % 3) * BSTG;
        const uint32_t bb = ab + 16384;

#pragma unroll
        for (int ksp = 0; ksp < 2; ksp++) {
            uint32_t bf[8][4];
#pragma unroll
            for (int nf = 0; nf < 8; nf++) {
                int row = wn0 + nf * 8 + rowB_l;
                LDSM_X4(bf[nf][0], bf[nf][1], bf[nf][2], bf[nf][3],
                        bb + SWZ(row, 4 * ksp + selB));
            }
#pragma unroll
            for (int k2 = 0; k2 < 2; k2++) {
                uint32_t af[4][4];
#pragma unroll
                for (int mf = 0; mf < 4; mf++) {
                    int row = wm0 + mf * 16 + rowA_l;
                    LDSM_X4(af[mf][0], af[mf][1], af[mf][2], af[mf][3],
                            ab + SWZ(row, 4 * ksp + 2 * k2 + selA));
                }
#pragma unroll
                for (int mf = 0; mf < 4; mf++)
#pragma unroll
                    for (int nf = 0; nf < 8; nf++)
                        mma_f16(acc[mf][nf],
                                af[mf][0], af[mf][1], af[mf][2], af[mf][3],
                                bf[nf][2 * k2], bf[nf][2 * k2 + 1]);
            }
        }
    }

    const bool vtile = (n0 >= 2 * HID);

#pragma unroll
    for (int nf = 0; nf < 8; nf++) {
        int c = n0 + wn0 + nf * 8 + 2 * q;
        float2 sc = *(const float2*)(scale + c);
        float2 sh = *(const float2*)(shift + c);
#pragma unroll
        for (int mf = 0; mf < 4; mf++) {
            int r = m0 + wm0 + mf * 16 + g;
            float v0 = acc[mf][nf][0] * sc.x + sh.x;
            float v1 = acc[mf][nf][1] * sc.y + sh.y;
            float v2 = acc[mf][nf][2] * sc.x + sh.x;
            float v3 = acc[mf][nf][3] * sc.y + sh.y;
            if (vtile) {
                int ch = c - 2 * HID;
                int h = ch >> 6, d = ch & 63;
                int bidx = r >> 10, s = r & 1023;
                __half* base = VT + (((size_t)bidx * NHEADS + h) << 16) + ((size_t)d << 10);
                base[s]            = __float2half_rn(v0);
                base[1024 + s]     = __float2half_rn(v1);
                base[s + 8]        = __float2half_rn(v2);
                base[1024 + s + 8] = __float2half_rn(v3);
            } else {
                *(__half2*)(Cout + (size_t)r * N + c) = __floats2half2_rn(v0, v1);
                *(__half2*)(Cout + (size_t)(r + 8) * N + c) = __floats2half2_rn(v2, v3);
            }
        }
    }
}

// ---------------------------------------------------------------------------
// fp16 GEMM 128x128 (round-9 proven version) — used for the out projection.
// ---------------------------------------------------------------------------
#define KT       64
#define NCH      (768/KT)
#define STG_BYT  32768
#define GEMM_SMEM (3 * STG_BYT)   // 98304

__global__ __launch_bounds__(256, 2)
void gemm_h(const __half* __restrict__ A, const __half* __restrict__ Bt,
            float* __restrict__ Cout, int N,
            const float* __restrict__ bias,
            const float* __restrict__ scale,
            const float* __restrict__ shift)
{
    extern __shared__ char smem[];
    const uint32_t sb = smem_u32(smem);
    const int tid  = threadIdx.x;
    const int lane = tid & 31;
    const int warp = tid >> 5;
    const int g = lane >> 2;
    const int q = lane & 3;
    const int wm0 = (warp >> 2) * 64;
    const int wn0 = (warp & 3) * 32;
    const int m0 = blockIdx.y * 128;
    const int n0 = blockIdx.x * 128;

    float acc[4][4][4];
#pragma unroll
    for (int mf = 0; mf < 4; mf++)
#pragma unroll
        for (int nf = 0; nf < 4; nf++)
#pragma unroll
            for (int cc = 0; cc < 4; cc++) acc[mf][nf][cc] = 0.f;

    const int r_ld = tid >> 3;
    const int u_ld = tid & 7;
    const int rowA_l = lane & 15;
    const int rowB_l = lane & 7;
    const int selA = lane >> 4;
    const int selB = lane >> 3;

#define LOAD_STAGE(s, kc) do { \
    uint32_t ab = sb + (s) * STG_BYT; \
    uint32_t bb = ab + 16384; \
    _Pragma("unroll") \
    for (int i = 0; i < 4; i++) { \
        int r = r_ld + i * 32; \
        uint32_t off = SWZ(r, u_ld); \
        cp16(ab + off, A  + (size_t)(m0 + r) * 768 + (kc) * KT + u_ld * 8); \
        cp16(bb + off, Bt + (size_t)(n0 + r) * 768 + (kc) * KT + u_ld * 8); \
    } \
} while (0)

    LOAD_STAGE(0, 0); CP_COMMIT();
    LOAD_STAGE(1, 1); CP_COMMIT();

    for (int kc = 0; kc < NCH; kc++) {
        if (kc == NCH - 1) { CP_WAIT0(); } else { CP_WAIT1(); }
        __syncthreads();
        if (kc + 2 < NCH) {
            LOAD_STAGE((kc + 2) % 3, kc + 2);
            CP_COMMIT();
        }
        const uint32_t ab = sb + (kc % 3) * STG_BYT;
        const uint32_t bb = ab + 16384;

#pragma unroll
        for (int ksp = 0; ksp < 2; ksp++) {
            uint32_t bf[4][4];
#pragma unroll
            for (int nf = 0; nf < 4; nf++) {
                int row = wn0 + nf * 8 + rowB_l;
                LDSM_X4(bf[nf][0], bf[nf][1], bf[nf][2], bf[nf][3],
                        bb + SWZ(row, 4 * ksp + selB));
            }
#pragma unroll
            for (int k2 = 0; k2 < 2; k2++) {
                uint32_t af[4][4];
#pragma unroll
                for (int mf = 0; mf < 4; mf++) {
                    int row = wm0 + mf * 16 + rowA_l;
                    LDSM_X4(af[mf][0], af[mf][1], af[mf][2], af[mf][3],
                            ab + SWZ(row, 4 * ksp + 2 * k2 + selA));
                }
#pragma unroll
                for (int mf = 0; mf < 4; mf++)
#pragma unroll
                    for (int nf = 0; nf < 4; nf++)
                        mma_f16(acc[mf][nf],
                                af[mf][0], af[mf][1], af[mf][2], af[mf][3],
                                bf[nf][2 * k2], bf[nf][2 * k2 + 1]);
            }
        }
    }

#pragma unroll
    for (int nf = 0; nf < 4; nf++) {
        int c = n0 + wn0 + nf * 8 + 2 * q;
        float2 sc = *(const float2*)(scale + c);
        float2 sh = *(const float2*)(shift + c);
        float2 bi = *(const float2*)(bias + c);
#pragma unroll
        for (int mf = 0; mf < 4; mf++) {
            int r = m0 + wm0 + mf * 16 + g;
            float2 lo, hi;
            lo.x = (acc[mf][nf][0] + bi.x) * sc.x + sh.x;
            lo.y = (acc[mf][nf][1] + bi.y) * sc.y + sh.y;
            hi.x = (acc[mf][nf][2] + bi.x) * sc.x + sh.x;
            hi.y = (acc[mf][nf][3] + bi.y) * sc.y + sh.y;
            *(float2*)(Cout + (size_t)r * N + c) = lo;
            *(float2*)(Cout + (size_t)(r + 8) * N + c) = hi;
        }
    }
}

// ---------------------------------------------------------------------------
// merged prep kernel
// ---------------------------------------------------------------------------
#define NB_X4  (MTOT*HID/4/1024)                   // 1536
#define NB_WQ  ((QKV_N/32) * (HID/32))             // 1728
#define NB_WO  ((HID/32) * (HID/32))               // 576
#define NB_SSF 9
#define NB_ALL (NB_X4 + NB_WQ + NB_WO + NB_SSF)
#define QPRE   0.18033688f                         // 0.125 * log2(e)

__global__ void prep_all(const float* __restrict__ x, __half* __restrict__ x_h,
                         const float* __restrict__ Wqkv, __half* __restrict__ wt_qkv,
                         const float* __restrict__ Wout, __half* __restrict__ wt_out,
                         const float* __restrict__ sc1, const float* __restrict__ sh1,
                         float* __restrict__ ssf)
{
    __shared__ float t[32][33];
    const int bid = blockIdx.x;
    const int tid = threadIdx.x;

    if (bid < NB_X4) {
        int base = bid * 1024 + tid;
#pragma unroll
        for (int it = 0; it < 4; it++) {
            int i = base + it * 256;
            float4 v = ((const float4*)x)[i];
            ((__half2*)x_h)[2 * i]     = __floats2half2_rn(v.x, v.y);
            ((__half2*)x_h)[2 * i + 1] = __floats2half2_rn(v.z, v.w);
        }
        return;
    }
    if (bid < NB_X4 + NB_WQ + NB_WO) {
        const float* in; __half* out; int R, C, idx;
        if (bid < NB_X4 + NB_WQ) {
            idx = bid - NB_X4; in = Wqkv; out = wt_qkv; R = HID; C = QKV_N;
        } else {
            idx = bid - NB_X4 - NB_WQ; in = Wout; out = wt_out; R = HID; C = HID;
        }
        int nbx = C / 32;
        int c0 = (idx % nbx) * 32, r0 = (idx / nbx) * 32;
        int tx = tid & 31, ty = tid >> 5;
#pragma unroll
        for (int i = 0; i < 32; i += 8)
            t[ty + i][tx] = in[(size_t)(r0 + ty + i) * C + c0 + tx];
        __syncthreads();
#pragma unroll
        for (int i = 0; i < 32; i += 8)
            out[(size_t)(c0 + ty + i) * R + r0 + tx] =
                __float2half_rn(t[tx][ty + i]);
        return;
    }
    {
        int i = (bid - (NB_X4 + NB_WQ + NB_WO)) * 256 + tid;
        if (i < QKV_N) {
            float f = (i < HID) ? QPRE : 1.0f;
            ssf[i]         = sc1[i] * f;
            ssf[QKV_N + i] = sh1[i] * f;
        }
    }
}

// ---------------------------------------------------------------------------
// fp16 flash attention — exact round-9 version (best: 224.6us).
// Fixed-max exp2 softmax (Q pre-scaled by 0.125*log2e), fp32 exp2f,
// P packed to fp16 A-frags, l via FADD + deferred shuffle reduction.
// ---------------------------------------------------------------------------
#define ATT_KB(s) (16384 + (s) * 8192)
#define ATT_VB(s) (32768 + (s) * 8192)
#define ATTN_SMEM 49152

__global__ __launch_bounds__(256, 2)
void attn_h(const __half* __restrict__ qkv, const __half* __restrict__ vt,
            __half* __restrict__ out)
{
    extern __shared__ char sm[];
    const uint32_t sb = smem_u32(sm);

    const int tid  = threadIdx.x;
    const int lane = tid & 31;
    const int warp = tid >> 5;
    const int g = lane >> 2;
    const int q = lane & 3;
    const int s0 = blockIdx.x * 128;
    const int bh = blockIdx.y;
    const int b = bh / NHEADS;
    const int h = bh - b * NHEADS;

    const __half* qbase = qkv + (size_t)b * SEQ * QKV_N + h * HDIM;
    const __half* kbase = qbase + HID;
    const __half* vtb   = vt + ((size_t)bh << 16);

    const int r_ld = tid >> 3;
    const int u_ld = tid & 7;

#define LOAD_KV(t_, s_) do { \
    int j0_ = (t_) * 64; \
    _Pragma("unroll") \
    for (int i = 0; i < 2; i++) { \
        int r = r_ld + i * 32; \
        uint32_t off = SWZ(r, u_ld); \
        cp16(sb + ATT_KB(s_) + off, kbase + (size_t)(j0_ + r) * QKV_N + u_ld * 8); \
        cp16(sb + ATT_VB(s_) + off, vtb + ((size_t)r << 10) + j0_ + u_ld * 8); \
    } \
} while (0)

#pragma unroll
    for (int i = 0; i < 4; i++) {
        int r = r_ld + i * 32;
        cp16(sb + SWZ(r, u_ld), qbase + (size_t)(s0 + r) * QKV_N + u_ld * 8);
    }
    LOAD_KV(0, 0);
    CP_COMMIT();

    float o_acc[8][4];
#pragma unroll
    for (int nf = 0; nf < 8; nf++)
#pragma unroll
        for (int cc = 0; cc < 4; cc++) o_acc[nf][cc] = 0.f;
    float l0r = 0.f, l1r = 0.f;

    const int qrow = warp * 16 + (lane & 15);
    const int qsel = lane >> 4;
    const int kfrow_l = lane & 7;
    const int kfsel = lane >> 3;

    for (int t = 0; t < SEQ / 64; t++) {
        CP_WAIT0();
        __syncthreads();
        if (t + 1 < SEQ / 64) {
            LOAD_KV(t + 1, (t + 1) & 1);
            CP_COMMIT();
        }
        const uint32_t kb_base = sb + ATT_KB(t & 1);
        const uint32_t vb_base = sb + ATT_VB(t & 1);

        float s[8][4];
#pragma unroll
        for (int nf = 0; nf < 8; nf++)
#pragma unroll
            for (int cc = 0; cc < 4; cc++) s[nf][cc] = 0.f;

#pragma unroll
        for (int ksp = 0; ksp < 2; ksp++) {
            uint32_t qa0[4], qa1[4];
            LDSM_X4(qa0[0], qa0[1], qa0[2], qa0[3], sb + SWZ(qrow, 4 * ksp + qsel));
            LDSM_X4(qa1[0], qa1[1], qa1[2], qa1[3], sb + SWZ(qrow, 4 * ksp + 2 + qsel));
#pragma unroll
            for (int nf = 0; nf < 8; nf++) {
                uint32_t kb[4];
                LDSM_X4(kb[0], kb[1], kb[2], kb[3],
                        kb_base + SWZ(nf * 8 + kfrow_l, 4 * ksp + kfsel));
                mma_f16(s[nf], qa0[0], qa0[1], qa0[2], qa0[3], kb[0], kb[1]);
                mma_f16(s[nf], qa1[0], qa1[1], qa1[2], qa1[3], kb[2], kb[3]);
            }
        }

#pragma unroll
        for (int nf = 0; nf < 8; nf++) {
            s[nf][0] = exp2f(s[nf][0]);
            s[nf][1] = exp2f(s[nf][1]);
            s[nf][2] = exp2f(s[nf][2]);
            s[nf][3] = exp2f(s[nf][3]);
            l0r += s[nf][0] + s[nf][1];
            l1r += s[nf][2] + s[nf][3];
        }

#pragma unroll
        for (int ksp = 0; ksp < 2; ksp++) {
            uint32_t vb[8][4];
#pragma unroll
            for (int nf = 0; nf < 8; nf++)
                LDSM_X4(vb[nf][0], vb[nf][1], vb[nf][2], vb[nf][3],
                        vb_base + SWZ(nf * 8 + kfrow_l, 4 * ksp + kfsel));
#pragma unroll
            for (int k2 = 0; k2 < 2; k2++) {
                int ks = 2 * ksp + k2;
                uint32_t pa0 = packh2(s[2 * ks][0], s[2 * ks][1]);
                uint32_t pa1 = packh2(s[2 * ks][2], s[2 * ks][3]);
                uint32_t pa2 = packh2(s[2 * ks + 1][0], s[2 * ks + 1][1]);
                uint32_t pa3 = packh2(s[2 * ks + 1][2], s[2 * ks + 1][3]);
#pragma unroll
                for (int nf = 0; nf < 8; nf++)
                    mma_f16(o_acc[nf], pa0, pa1, pa2, pa3,
                            vb[nf][2 * k2], vb[nf][2 * k2 + 1]);
            }
        }
    }

    l0r += __shfl_xor_sync(0xffffffffu, l0r, 1);
    l0r += __shfl_xor_sync(0xffffffffu, l0r, 2);
    l1r += __shfl_xor_sync(0xffffffffu, l1r, 1);
    l1r += __shfl_xor_sync(0xffffffffu, l1r, 2);
    float inv0 = 1.0f / l0r;
    float inv1 = 1.0f / l1r;
    int r0 = b * SEQ + s0 + warp * 16 + g;
#pragma unroll
    for (int nf = 0; nf < 8; nf++) {
        int c = h * HDIM + nf * 8 + 2 * q;
        *(__half2*)(out + (size_t)r0 * HID + c) =
            __floats2half2_rn(o_acc[nf][0] * inv0, o_acc[nf][1] * inv0);
        *(__half2*)(out + (size_t)(r0 + 8) * HID + c) =
            __floats2half2_rn(o_acc[nf][2] * inv1, o_acc[nf][3] * inv1);
    }
}

// ---------------------------------------------------------------------------
extern "C" void kernel_launch(void* const* d_in, const int* in_sizes, int n_in,
                              void* d_out, int out_size)
{
    (void)in_sizes; (void)n_in; (void)out_size;
    const float* x      = (const float*)d_in[0];
    const float* Wqkv   = (const float*)d_in[1];
    const float* scale1 = (const float*)d_in[2];
    const float* shift1 = (const float*)d_in[3];
    const float* Wout   = (const float*)d_in[4];
    const float* bout   = (const float*)d_in[5];
    const float* scale2 = (const float*)d_in[6];
    const float* shift2 = (const float*)d_in[7];
    float* out = (float*)d_out;

    __half *x_h, *qkv_h, *vt_h, *o_h, *wt_qkv, *wt_out;
    float* ssf;
    cudaGetSymbolAddress((void**)&x_h, g_x);
    cudaGetSymbolAddress((void**)&qkv_h, g_qkv);
    cudaGetSymbolAddress((void**)&vt_h, g_vt);
    cudaGetSymbolAddress((void**)&o_h, g_o);
    cudaGetSymbolAddress((void**)&wt_qkv, g_wt_qkv);
    cudaGetSymbolAddress((void**)&wt_out, g_wt_out);
    cudaGetSymbolAddress((void**)&ssf, g_ssf);

    static bool attr_set = false;
    if (!attr_set) {
        cudaFuncSetAttribute(gemm_big, cudaFuncAttributeMaxDynamicSharedMemorySize, BGEMM_SMEM);
        cudaFuncSetAttribute(gemm_h, cudaFuncAttributeMaxDynamicSharedMemorySize, GEMM_SMEM);
        cudaFuncSetAttribute(attn_h, cudaFuncAttributeMaxDynamicSharedMemorySize, ATTN_SMEM);
        attr_set = true;
    }

    // 0) merged prep
    prep_all<<<NB_ALL, 256>>>(x, x_h, Wqkv, wt_qkv, Wout, wt_out,
                              scale1, shift1, ssf);
    // 1) QKV projection + SSF affine (big-tile kernel; fp16 out, V transposed)
    gemm_big<<<dim3(QKV_N / 256, MTOT / 128), 256, BGEMM_SMEM>>>(
        x_h, wt_qkv, qkv_h, QKV_N, ssf, ssf + QKV_N, vt_h);
    // 2) attention (round-9 version)
    attn_h<<<dim3(SEQ / 128, BATCH * NHEADS), 256, ATTN_SMEM>>>(qkv_h, vt_h, o_h);
    // 3) out projection + bias + SSF affine (fp32 exact epilogue)
    gemm_h<<<dim3(HID / 128, MTOT / 128), 256, GEMM_SMEM>>>(
        o_h, wt_out, out, HID, bout, scale2, shift2);
}

// round 13
// speedup vs baseline: 1.0461x; 1.0375x over previous
#include <cuda_runtime.h>
#include <cuda_fp16.h>
#include <math.h>
#include <stdint.h>

#define BATCH   8
#define SEQ     1024
#define HID     768
#define NHEADS  12
#define HDIM    64
#define QKV_N   (3*HID)          // 2304
#define MTOT    (BATCH*SEQ)      // 8192

__device__ __half g_x[(size_t)MTOT * HID];
__device__ __half g_qkv[(size_t)MTOT * QKV_N];
__device__ __half g_vt[(size_t)BATCH * NHEADS * HDIM * SEQ];  // V^T [bh][d][s]
__device__ __half g_o[(size_t)MTOT * HID];
__device__ __half g_wt_qkv[(size_t)QKV_N * HID];
__device__ __half g_wt_out[(size_t)HID * HID];
__device__ float  g_ssf[2 * QKV_N];     // Q-prescaled scale1/shift1
__device__ float  g_ssf2[2 * HID];      // scale2, bout*scale2+shift2

// ---------------------------------------------------------------------------
// helpers
// ---------------------------------------------------------------------------
__device__ __forceinline__ uint32_t smem_u32(const void* p) {
    uint32_t a;
    asm("{ .reg .u64 t; cvta.to.shared.u64 t, %1; cvt.u32.u64 %0, t; }" : "=r"(a) : "l"(p));
    return a;
}
__device__ __forceinline__ uint32_t packh2(float lo, float hi) {
    __half2 h = __floats2half2_rn(lo, hi);
    return *reinterpret_cast<uint32_t*>(&h);
}
__device__ __forceinline__ void mma_f16(float* c,
                                        uint32_t a0, uint32_t a1, uint32_t a2, uint32_t a3,
                                        uint32_t b0, uint32_t b1) {
    asm volatile(
        "mma.sync.aligned.m16n8k16.row.col.f32.f16.f16.f32 "
        "{%0,%1,%2,%3}, {%4,%5,%6,%7}, {%8,%9}, {%0,%1,%2,%3};"
        : "+f"(c[0]), "+f"(c[1]), "+f"(c[2]), "+f"(c[3])
        : "r"(a0), "r"(a1), "r"(a2), "r"(a3), "r"(b0), "r"(b1));
}
#define LDSM_X4(r0, r1, r2, r3, addr) \
    asm volatile("ldmatrix.sync.aligned.m8n8.x4.shared.b16 {%0,%1,%2,%3}, [%4];" \
        : "=r"(r0), "=r"(r1), "=r"(r2), "=r"(r3) : "r"(addr))
__device__ __forceinline__ void cp16(uint32_t dst, const void* src) {
    asm volatile("cp.async.cg.shared.global [%0], [%1], 16;" :: "r"(dst), "l"(src));
}
#define CP_COMMIT() asm volatile("cp.async.commit_group;" ::: "memory")
#define CP_WAIT1()  asm volatile("cp.async.wait_group 1;" ::: "memory")
#define CP_WAIT0()  asm volatile("cp.async.wait_group 0;" ::: "memory")

#define SWZ(r, u) (((((uint32_t)(r)) << 3) + (((uint32_t)(u)) ^ (((uint32_t)(r)) & 7))) << 4)

// ---------------------------------------------------------------------------
// fp16 GEMM 128x128 (round-9 proven) — QKV projection.
// fp16 out + SSF affine; V channel tiles written transposed to VT.
// ---------------------------------------------------------------------------
#define KT       64
#define NCH      (768/KT)
#define STG_BYT  32768
#define GEMM_SMEM (3 * STG_BYT)   // 98304

__global__ __launch_bounds__(256, 2)
void gemm_h(const __half* __restrict__ A, const __half* __restrict__ Bt,
            __half* __restrict__ Cout, int N,
            const float* __restrict__ scale,
            const float* __restrict__ shift,
            __half* __restrict__ VT)
{
    extern __shared__ char smem[];
    const uint32_t sb = smem_u32(smem);
    const int tid  = threadIdx.x;
    const int lane = tid & 31;
    const int warp = tid >> 5;
    const int g = lane >> 2;
    const int q = lane & 3;
    const int wm0 = (warp >> 2) * 64;
    const int wn0 = (warp & 3) * 32;
    const int m0 = blockIdx.y * 128;
    const int n0 = blockIdx.x * 128;

    float acc[4][4][4];
#pragma unroll
    for (int mf = 0; mf < 4; mf++)
#pragma unroll
        for (int nf = 0; nf < 4; nf++)
#pragma unroll
            for (int cc = 0; cc < 4; cc++) acc[mf][nf][cc] = 0.f;

    const int r_ld = tid >> 3;
    const int u_ld = tid & 7;
    const int rowA_l = lane & 15;
    const int rowB_l = lane & 7;
    const int selA = lane >> 4;
    const int selB = lane >> 3;

#define LOAD_STAGE(s, kc) do { \
    uint32_t ab = sb + (s) * STG_BYT; \
    uint32_t bb = ab + 16384; \
    _Pragma("unroll") \
    for (int i = 0; i < 4; i++) { \
        int r = r_ld + i * 32; \
        uint32_t off = SWZ(r, u_ld); \
        cp16(ab + off, A  + (size_t)(m0 + r) * 768 + (kc) * KT + u_ld * 8); \
        cp16(bb + off, Bt + (size_t)(n0 + r) * 768 + (kc) * KT + u_ld * 8); \
    } \
} while (0)

    LOAD_STAGE(0, 0); CP_COMMIT();
    LOAD_STAGE(1, 1); CP_COMMIT();

    for (int kc = 0; kc < NCH; kc++) {
        if (kc == NCH - 1) { CP_WAIT0(); } else { CP_WAIT1(); }
        __syncthreads();
        if (kc + 2 < NCH) {
            LOAD_STAGE((kc + 2) % 3, kc + 2);
            CP_COMMIT();
        }
        const uint32_t ab = sb + (kc % 3) * STG_BYT;
        const uint32_t bb = ab + 16384;

#pragma unroll
        for (int ksp = 0; ksp < 2; ksp++) {
            uint32_t bf[4][4];
#pragma unroll
            for (int nf = 0; nf < 4; nf++) {
                int row = wn0 + nf * 8 + rowB_l;
                LDSM_X4(bf[nf][0], bf[nf][1], bf[nf][2], bf[nf][3],
                        bb + SWZ(row, 4 * ksp + selB));
            }
#pragma unroll
            for (int k2 = 0; k2 < 2; k2++) {
                uint32_t af[4][4];
#pragma unroll
                for (int mf = 0; mf < 4; mf++) {
                    int row = wm0 + mf * 16 + rowA_l;
                    LDSM_X4(af[mf][0], af[mf][1], af[mf][2], af[mf][3],
                            ab + SWZ(row, 4 * ksp + 2 * k2 + selA));
                }
#pragma unroll
                for (int mf = 0; mf < 4; mf++)
#pragma unroll
                    for (int nf = 0; nf < 4; nf++)
                        mma_f16(acc[mf][nf],
                                af[mf][0], af[mf][1], af[mf][2], af[mf][3],
                                bf[nf][2 * k2], bf[nf][2 * k2 + 1]);
            }
        }
    }

    const bool vtile = (n0 >= 2 * HID);

#pragma unroll
    for (int nf = 0; nf < 4; nf++) {
        int c = n0 + wn0 + nf * 8 + 2 * q;
        float2 sc = *(const float2*)(scale + c);
        float2 sh = *(const float2*)(shift + c);
#pragma unroll
        for (int mf = 0; mf < 4; mf++) {
            int r = m0 + wm0 + mf * 16 + g;
            float v0 = acc[mf][nf][0] * sc.x + sh.x;
            float v1 = acc[mf][nf][1] * sc.y + sh.y;
            float v2 = acc[mf][nf][2] * sc.x + sh.x;
            float v3 = acc[mf][nf][3] * sc.y + sh.y;
            if (vtile) {
                int ch = c - 2 * HID;
                int h = ch >> 6, d = ch & 63;
                int bidx = r >> 10, s = r & 1023;
                __half* base = VT + (((size_t)bidx * NHEADS + h) << 16) + ((size_t)d << 10);
                base[s]            = __float2half_rn(v0);
                base[1024 + s]     = __float2half_rn(v1);
                base[s + 8]        = __float2half_rn(v2);
                base[1024 + s + 8] = __float2half_rn(v3);
            } else {
                *(__half2*)(Cout + (size_t)r * N + c) = __floats2half2_rn(v0, v1);
                *(__half2*)(Cout + (size_t)(r + 8) * N + c) = __floats2half2_rn(v2, v3);
            }
        }
    }
}

// ---------------------------------------------------------------------------
// fp16 GEMM 64x128 — out projection (768 CTAs -> better wave balance).
// Warp tile 32x32 (2x4 warps). fp32 out with pre-folded affine (ssf2).
// ---------------------------------------------------------------------------
#define OSTG_BYT  24576          // A 8KB + B 16KB
#define OGEMM_SMEM (3 * OSTG_BYT)   // 73728

__global__ __launch_bounds__(256, 2)
void gemm64(const __half* __restrict__ A, const __half* __restrict__ Bt,
            float* __restrict__ Cout,
            const float* __restrict__ ssf2)
{
    extern __shared__ char smem[];
    const uint32_t sb = smem_u32(smem);
    const int tid  = threadIdx.x;
    const int lane = tid & 31;
    const int warp = tid >> 5;
    const int g = lane >> 2;
    const int q = lane & 3;
    const int wm0 = (warp >> 2) * 32;   // 0 / 32
    const int wn0 = (warp & 3) * 32;
    const int m0 = blockIdx.y * 64;
    const int n0 = blockIdx.x * 128;

    float acc[2][4][4];
#pragma unroll
    for (int mf = 0; mf < 2; mf++)
#pragma unroll
        for (int nf = 0; nf < 4; nf++)
#pragma unroll
            for (int cc = 0; cc < 4; cc++) acc[mf][nf][cc] = 0.f;

    const int r_ld = tid >> 3;     // 0..31
    const int u_ld = tid & 7;
    const int rowA_l = lane & 15;
    const int rowB_l = lane & 7;
    const int selA = lane >> 4;
    const int selB = lane >> 3;

#define OLOAD_STAGE(s, kc) do { \
    uint32_t ab = sb + (s) * OSTG_BYT; \
    uint32_t bb = ab + 8192; \
    _Pragma("unroll") \
    for (int i = 0; i < 2; i++) { \
        int r = r_ld + i * 32; \
        cp16(ab + SWZ(r, u_ld), A + (size_t)(m0 + r) * 768 + (kc) * KT + u_ld * 8); \
    } \
    _Pragma("unroll") \
    for (int i = 0; i < 4; i++) { \
        int r = r_ld + i * 32; \
        cp16(bb + SWZ(r, u_ld), Bt + (size_t)(n0 + r) * 768 + (kc) * KT + u_ld * 8); \
    } \
} while (0)

    OLOAD_STAGE(0, 0); CP_COMMIT();
    OLOAD_STAGE(1, 1); CP_COMMIT();

    for (int kc = 0; kc < NCH; kc++) {
        if (kc == NCH - 1) { CP_WAIT0(); } else { CP_WAIT1(); }
        __syncthreads();
        if (kc + 2 < NCH) {
            OLOAD_STAGE((kc + 2) % 3, kc + 2);
            CP_COMMIT();
        }
        const uint32_t ab = sb + (kc % 3) * OSTG_BYT;
        const uint32_t bb = ab + 8192;

#pragma unroll
        for (int ksp = 0; ksp < 2; ksp++) {
            uint32_t bf[4][4];
#pragma unroll
            for (int nf = 0; nf < 4; nf++) {
                int row = wn0 + nf * 8 + rowB_l;
                LDSM_X4(bf[nf][0], bf[nf][1], bf[nf][2], bf[nf][3],
                        bb + SWZ(row, 4 * ksp + selB));
            }
#pragma unroll
            for (int k2 = 0; k2 < 2; k2++) {
                uint32_t af[2][4];
#pragma unroll
                for (int mf = 0; mf < 2; mf++) {
                    int row = wm0 + mf * 16 + rowA_l;
                    LDSM_X4(af[mf][0], af[mf][1], af[mf][2], af[mf][3],
                            ab + SWZ(row, 4 * ksp + 2 * k2 + selA));
                }
#pragma unroll
                for (int mf = 0; mf < 2; mf++)
#pragma unroll
                    for (int nf = 0; nf < 4; nf++)
                        mma_f16(acc[mf][nf],
                                af[mf][0], af[mf][1], af[mf][2], af[mf][3],
                                bf[nf][2 * k2], bf[nf][2 * k2 + 1]);
            }
        }
    }

#pragma unroll
    for (int nf = 0; nf < 4; nf++) {
        int c = n0 + wn0 + nf * 8 + 2 * q;
        float2 sc = *(const float2*)(ssf2 + c);
        float2 sh = *(const float2*)(ssf2 + HID + c);
#pragma unroll
        for (int mf = 0; mf < 2; mf++) {
            int r = m0 + wm0 + mf * 16 + g;
            float2 lo, hi;
            lo.x = acc[mf][nf][0] * sc.x + sh.x;
            lo.y = acc[mf][nf][1] * sc.y + sh.y;
            hi.x = acc[mf][nf][2] * sc.x + sh.x;
            hi.y = acc[mf][nf][3] * sc.y + sh.y;
            *(float2*)(Cout + (size_t)r * HID + c) = lo;
            *(float2*)(Cout + (size_t)(r + 8) * HID + c) = hi;
        }
    }
}

// ---------------------------------------------------------------------------
// merged prep kernel
// ---------------------------------------------------------------------------
#define NB_X4   (MTOT*HID/4/1024)                  // 1536
#define NB_WQ   ((QKV_N/32) * (HID/32))            // 1728
#define NB_WO   ((HID/32) * (HID/32))              // 576
#define NB_SSF  9
#define NB_SSF2 3
#define NB_ALL  (NB_X4 + NB_WQ + NB_WO + NB_SSF + NB_SSF2)
#define QPRE    0.18033688f                        // 0.125 * log2(e)

__global__ void prep_all(const float* __restrict__ x, __half* __restrict__ x_h,
                         const float* __restrict__ Wqkv, __half* __restrict__ wt_qkv,
                         const float* __restrict__ Wout, __half* __restrict__ wt_out,
                         const float* __restrict__ sc1, const float* __restrict__ sh1,
                         float* __restrict__ ssf,
                         const float* __restrict__ bout,
                         const float* __restrict__ sc2, const float* __restrict__ sh2,
                         float* __restrict__ ssf2)
{
    __shared__ float t[32][33];
    const int bid = blockIdx.x;
    const int tid = threadIdx.x;

    if (bid < NB_X4) {
        int base = bid * 1024 + tid;
#pragma unroll
        for (int it = 0; it < 4; it++) {
            int i = base + it * 256;
            float4 v = ((const float4*)x)[i];
            ((__half2*)x_h)[2 * i]     = __floats2half2_rn(v.x, v.y);
            ((__half2*)x_h)[2 * i + 1] = __floats2half2_rn(v.z, v.w);
        }
        return;
    }
    if (bid < NB_X4 + NB_WQ + NB_WO) {
        const float* in; __half* out; int R, C, idx;
        if (bid < NB_X4 + NB_WQ) {
            idx = bid - NB_X4; in = Wqkv; out = wt_qkv; R = HID; C = QKV_N;
        } else {
            idx = bid - NB_X4 - NB_WQ; in = Wout; out = wt_out; R = HID; C = HID;
        }
        int nbx = C / 32;
        int c0 = (idx % nbx) * 32, r0 = (idx / nbx) * 32;
        int tx = tid & 31, ty = tid >> 5;
#pragma unroll
        for (int i = 0; i < 32; i += 8)
            t[ty + i][tx] = in[(size_t)(r0 + ty + i) * C + c0 + tx];
        __syncthreads();
#pragma unroll
        for (int i = 0; i < 32; i += 8)
            out[(size_t)(c0 + ty + i) * R + r0 + tx] =
                __float2half_rn(t[tx][ty + i]);
        return;
    }
    if (bid < NB_X4 + NB_WQ + NB_WO + NB_SSF) {
        int i = (bid - (NB_X4 + NB_WQ + NB_WO)) * 256 + tid;
        if (i < QKV_N) {
            float f = (i < HID) ? QPRE : 1.0f;
            ssf[i]         = sc1[i] * f;
            ssf[QKV_N + i] = sh1[i] * f;
        }
        return;
    }
    {
        int i = (bid - (NB_X4 + NB_WQ + NB_WO + NB_SSF)) * 256 + tid;
        if (i < HID) {
            float s = sc2[i];
            ssf2[i]       = s;
            ssf2[HID + i] = fmaf(bout[i], s, sh2[i]);
        }
    }
}

// ---------------------------------------------------------------------------
// fp16 flash attention — round-9 exact version.
// ---------------------------------------------------------------------------
#define ATT_KB(s) (16384 + (s) * 8192)
#define ATT_VB(s) (32768 + (s) * 8192)
#define ATTN_SMEM 49152

__global__ __launch_bounds__(256, 2)
void attn_h(const __half* __restrict__ qkv, const __half* __restrict__ vt,
            __half* __restrict__ out)
{
    extern __shared__ char sm[];
    const uint32_t sb = smem_u32(sm);

    const int tid  = threadIdx.x;
    const int lane = tid & 31;
    const int warp = tid >> 5;
    const int g = lane >> 2;
    const int q = lane & 3;
    const int s0 = blockIdx.x * 128;
    const int bh = blockIdx.y;
    const int b = bh / NHEADS;
    const int h = bh - b * NHEADS;

    const __half* qbase = qkv + (size_t)b * SEQ * QKV_N + h * HDIM;
    const __half* kbase = qbase + HID;
    const __half* vtb   = vt + ((size_t)bh << 16);

    const int r_ld = tid >> 3;
    const int u_ld = tid & 7;

#define LOAD_KV(t_, s_) do { \
    int j0_ = (t_) * 64; \
    _Pragma("unroll") \
    for (int i = 0; i < 2; i++) { \
        int r = r_ld + i * 32; \
        uint32_t off = SWZ(r, u_ld); \
        cp16(sb + ATT_KB(s_) + off, kbase + (size_t)(j0_ + r) * QKV_N + u_ld * 8); \
        cp16(sb + ATT_VB(s_) + off, vtb + ((size_t)r << 10) + j0_ + u_ld * 8); \
    } \
} while (0)

#pragma unroll
    for (int i = 0; i < 4; i++) {
        int r = r_ld + i * 32;
        cp16(sb + SWZ(r, u_ld), qbase + (size_t)(s0 + r) * QKV_N + u_ld * 8);
    }
    LOAD_KV(0, 0);
    CP_COMMIT();

    float o_acc[8][4];
#pragma unroll
    for (int nf = 0; nf < 8; nf++)
#pragma unroll
        for (int cc = 0; cc < 4; cc++) o_acc[nf][cc] = 0.f;
    float l0r = 0.f, l1r = 0.f;

    const int qrow = warp * 16 + (lane & 15);
    const int qsel = lane >> 4;
    const int kfrow_l = lane & 7;
    const int kfsel = lane >> 3;

    for (int t = 0; t < SEQ / 64; t++) {
        CP_WAIT0();
        __syncthreads();
        if (t + 1 < SEQ / 64) {
            LOAD_KV(t + 1, (t + 1) & 1);
            CP_COMMIT();
        }
        const uint32_t kb_base = sb + ATT_KB(t & 1);
        const uint32_t vb_base = sb + ATT_VB(t & 1);

        float s[8][4];
#pragma unroll
        for (int nf = 0; nf < 8; nf++)
#pragma unroll
            for (int cc = 0; cc < 4; cc++) s[nf][cc] = 0.f;

#pragma unroll
        for (int ksp = 0; ksp < 2; ksp++) {
            uint32_t qa0[4], qa1[4];
            LDSM_X4(qa0[0], qa0[1], qa0[2], qa0[3], sb + SWZ(qrow, 4 * ksp + qsel));
            LDSM_X4(qa1[0], qa1[1], qa1[2], qa1[3], sb + SWZ(qrow, 4 * ksp + 2 + qsel));
#pragma unroll
            for (int nf = 0; nf < 8; nf++) {
                uint32_t kb[4];
                LDSM_X4(kb[0], kb[1], kb[2], kb[3],
                        kb_base + SWZ(nf * 8 + kfrow_l, 4 * ksp + kfsel));
                mma_f16(s[nf], qa0[0], qa0[1], qa0[2], qa0[3], kb[0], kb[1]);
                mma_f16(s[nf], qa1[0], qa1[1], qa1[2], qa1[3], kb[2], kb[3]);
            }
        }

#pragma unroll
        for (int nf = 0; nf < 8; nf++) {
            s[nf][0] = exp2f(s[nf][0]);
            s[nf][1] = exp2f(s[nf][1]);
            s[nf][2] = exp2f(s[nf][2]);
            s[nf][3] = exp2f(s[nf][3]);
            l0r += s[nf][0] + s[nf][1];
            l1r += s[nf][2] + s[nf][3];
        }

#pragma unroll
        for (int ksp = 0; ksp < 2; ksp++) {
            uint32_t vb[8][4];
#pragma unroll
            for (int nf = 0; nf < 8; nf++)
                LDSM_X4(vb[nf][0], vb[nf][1], vb[nf][2], vb[nf][3],
                        vb_base + SWZ(nf * 8 + kfrow_l, 4 * ksp + kfsel));
#pragma unroll
            for (int k2 = 0; k2 < 2; k2++) {
                int ks = 2 * ksp + k2;
                uint32_t pa0 = packh2(s[2 * ks][0], s[2 * ks][1]);
                uint32_t pa1 = packh2(s[2 * ks][2], s[2 * ks][3]);
                uint32_t pa2 = packh2(s[2 * ks + 1][0], s[2 * ks + 1][1]);
                uint32_t pa3 = packh2(s[2 * ks + 1][2], s[2 * ks + 1][3]);
#pragma unroll
                for (int nf = 0; nf < 8; nf++)
                    mma_f16(o_acc[nf], pa0, pa1, pa2, pa3,
                            vb[nf][2 * k2], vb[nf][2 * k2 + 1]);
            }
        }
    }

    l0r += __shfl_xor_sync(0xffffffffu, l0r, 1);
    l0r += __shfl_xor_sync(0xffffffffu, l0r, 2);
    l1r += __shfl_xor_sync(0xffffffffu, l1r, 1);
    l1r += __shfl_xor_sync(0xffffffffu, l1r, 2);
    float inv0 = 1.0f / l0r;
    float inv1 = 1.0f / l1r;
    int r0 = b * SEQ + s0 + warp * 16 + g;
#pragma unroll
    for (int nf = 0; nf < 8; nf++) {
        int c = h * HDIM + nf * 8 + 2 * q;
        *(__half2*)(out + (size_t)r0 * HID + c) =
            __floats2half2_rn(o_acc[nf][0] * inv0, o_acc[nf][1] * inv0);
        *(__half2*)(out + (size_t)(r0 + 8) * HID + c) =
            __floats2half2_rn(o_acc[nf][2] * inv1, o_acc[nf][3] * inv1);
    }
}

// ---------------------------------------------------------------------------
extern "C" void kernel_launch(void* const* d_in, const int* in_sizes, int n_in,
                              void* d_out, int out_size)
{
    (void)in_sizes; (void)n_in; (void)out_size;
    const float* x      = (const float*)d_in[0];
    const float* Wqkv   = (const float*)d_in[1];
    const float* scale1 = (const float*)d_in[2];
    const float* shift1 = (const float*)d_in[3];
    const float* Wout   = (const float*)d_in[4];
    const float* bout   = (const float*)d_in[5];
    const float* scale2 = (const float*)d_in[6];
    const float* shift2 = (const float*)d_in[7];
    float* out = (float*)d_out;

    __half *x_h, *qkv_h, *vt_h, *o_h, *wt_qkv, *wt_out;
    float *ssf, *ssf2;
    cudaGetSymbolAddress((void**)&x_h, g_x);
    cudaGetSymbolAddress((void**)&qkv_h, g_qkv);
    cudaGetSymbolAddress((void**)&vt_h, g_vt);
    cudaGetSymbolAddress((void**)&o_h, g_o);
    cudaGetSymbolAddress((void**)&wt_qkv, g_wt_qkv);
    cudaGetSymbolAddress((void**)&wt_out, g_wt_out);
    cudaGetSymbolAddress((void**)&ssf, g_ssf);
    cudaGetSymbolAddress((void**)&ssf2, g_ssf2);

    static bool attr_set = false;
    if (!attr_set) {
        cudaFuncSetAttribute(gemm_h, cudaFuncAttributeMaxDynamicSharedMemorySize, GEMM_SMEM);
        cudaFuncSetAttribute(gemm64, cudaFuncAttributeMaxDynamicSharedMemorySize, OGEMM_SMEM);
        cudaFuncSetAttribute(attn_h, cudaFuncAttributeMaxDynamicSharedMemorySize, ATTN_SMEM);
        attr_set = true;
    }

    // 0) merged prep
    prep_all<<<NB_ALL, 256>>>(x, x_h, Wqkv, wt_qkv, Wout, wt_out,
                              scale1, shift1, ssf,
                              bout, scale2, shift2, ssf2);
    // 1) QKV projection + SSF affine (128x128; fp16 out, V transposed)
    gemm_h<<<dim3(QKV_N / 128, MTOT / 128), 256, GEMM_SMEM>>>(
        x_h, wt_qkv, qkv_h, QKV_N, ssf, ssf + QKV_N, vt_h);
    // 2) attention (round-9 version)
    attn_h<<<dim3(SEQ / 128, BATCH * NHEADS), 256, ATTN_SMEM>>>(qkv_h, vt_h, o_h);
    // 3) out projection, 64-row tiles for wave balance (affine pre-folded)
    gemm64<<<dim3(HID / 128, MTOT / 64), 256, OGEMM_SMEM>>>(
        o_h, wt_out, out, ssf2);
}